// round 3
// baseline (speedup 1.0000x reference)
#include <cuda_runtime.h>
#include <math.h>
#include <stdint.h>

#define TT 2048
#define HH 1024
#define DD 512
#define EE 64
#define TOPK 2
#define NTILES 192

// ---------------- scratch (device globals; no allocation allowed) ----------------
__device__ int   g_topk_i[TT * TOPK];
__device__ float g_topk_w[TT * TOPK];
__device__ int   g_counts[EE];
__device__ int   g_list[EE * TT];              // pairid = t*2+k entries, grouped by expert
__device__ float g_act[TT * TOPK * DD];        // 8 MB activation scratch
__device__ float g_usage_partial[64 * EE];     // [router_block][expert]
__device__ int2  g_tiles[NTILES];              // {expert, m0}; -1-padded

// ---------------- zero out + counts ----------------
__global__ void k_zero(float* __restrict__ out) {
    int i = blockIdx.x * blockDim.x + threadIdx.x;
    int stride = gridDim.x * blockDim.x;
    for (int j = i; j < TT * HH; j += stride) out[j] = 0.f;
    if (i < EE) g_counts[i] = 0;
}

// ---------------- router: logits GEMM + top2 + softmax stats ----------------
// one block per 32 tokens; 256 threads
__global__ __launch_bounds__(256) void k_router(const float* __restrict__ x,
                                                const float* __restrict__ gate) {
    __shared__ float Xs[32][33];
    __shared__ float Gs[32][68];
    __shared__ float Ls[32][65];
    __shared__ float sM[32], sInv[32];

    const int t0 = blockIdx.x * 32;
    const int tid = threadIdx.x;
    const int tx = tid & 15, ty = tid >> 4;

    float acc[2][4];
#pragma unroll
    for (int i = 0; i < 2; i++)
#pragma unroll
        for (int j = 0; j < 4; j++) acc[i][j] = 0.f;

    for (int k0 = 0; k0 < HH; k0 += 32) {
        {
            int m = tid >> 3, k4 = (tid & 7) * 4;
            float4 v = *(const float4*)(x + (size_t)(t0 + m) * HH + k0 + k4);
            Xs[m][k4 + 0] = v.x; Xs[m][k4 + 1] = v.y;
            Xs[m][k4 + 2] = v.z; Xs[m][k4 + 3] = v.w;
        }
        {
            int k = tid >> 4, j4 = (tid & 15) * 4;
#pragma unroll
            for (int r = 0; r < 2; r++) {
                float4 v = *(const float4*)(gate + (size_t)(k0 + k + r * 16) * EE + j4);
                *(float4*)&Gs[k + r * 16][j4] = v;
            }
        }
        __syncthreads();
#pragma unroll
        for (int kk = 0; kk < 32; kk++) {
            float a0 = Xs[ty * 2 + 0][kk];
            float a1 = Xs[ty * 2 + 1][kk];
            float4 b = *(float4*)&Gs[kk][tx * 4];
            acc[0][0] += a0 * b.x; acc[0][1] += a0 * b.y; acc[0][2] += a0 * b.z; acc[0][3] += a0 * b.w;
            acc[1][0] += a1 * b.x; acc[1][1] += a1 * b.y; acc[1][2] += a1 * b.z; acc[1][3] += a1 * b.w;
        }
        __syncthreads();
    }
#pragma unroll
    for (int mi = 0; mi < 2; mi++)
#pragma unroll
        for (int ni = 0; ni < 4; ni++)
            Ls[ty * 2 + mi][tx * 4 + ni] = acc[mi][ni];
    __syncthreads();

    if (tid < 32) {
        int t = t0 + tid;
        float m1 = -1e30f, m2 = -1e30f;
        int i1 = -1, i2 = -1;
        for (int e = 0; e < EE; e++) {
            float l = Ls[tid][e];
            if (l > m1) { m2 = m1; i2 = i1; m1 = l; i1 = e; }
            else if (l > m2) { m2 = l; i2 = e; }
        }
        float den = 0.f;
        for (int e = 0; e < EE; e++) den += __expf(Ls[tid][e] - m1);
        sM[tid] = m1; sInv[tid] = 1.f / den;
        float e2 = __expf(m2 - m1);
        float s = 1.f + e2;
        g_topk_i[t * 2 + 0] = i1;
        g_topk_i[t * 2 + 1] = i2;
        g_topk_w[t * 2 + 0] = 1.f / s;
        g_topk_w[t * 2 + 1] = e2 / s;
    }
    __syncthreads();

    if (tid < EE) {
        float s = 0.f;
        for (int r = 0; r < 32; r++)
            s += __expf(Ls[r][tid] - sM[r]) * sInv[r];
        g_usage_partial[blockIdx.x * EE + tid] = s;
    }
}

// ---------------- lb loss ----------------
__global__ void k_lb(float* __restrict__ out_lb) {
    __shared__ float red[64];
    int e = threadIdx.x;
    float s = 0.f;
    for (int b = 0; b < 64; b++) s += g_usage_partial[b * EE + e];
    float u = s / (float)TT;
    red[e] = u * u;
    __syncthreads();
    for (int off = 32; off > 0; off >>= 1) {
        if (e < off) red[e] += red[e + off];
        __syncthreads();
    }
    if (e == 0) *out_lb = (float)EE * red[0];
}

// ---------------- build per-expert token lists ----------------
__global__ void k_build_lists() {
    int t = blockIdx.x * blockDim.x + threadIdx.x;
    if (t < TT) {
#pragma unroll
        for (int k = 0; k < TOPK; k++) {
            int e = g_topk_i[t * 2 + k];
            int pos = atomicAdd(&g_counts[e], 1);
            g_list[e * TT + pos] = t * 2 + k;
        }
    }
}

// ---------------- build tile list (parallel; fixed grid for graph capture) ----------------
__global__ void k_build_tiles() {
    __shared__ int sNT[EE];
    __shared__ int sBase[EE];
    int e = threadIdx.x;  // 64 threads
    // pad all slots
    for (int i = e; i < NTILES; i += 64) g_tiles[i] = make_int2(-1, 0);
    int nt = (g_counts[e] + 31) >> 5;
    sNT[e] = nt;
    __syncthreads();
    if (e == 0) {
        int acc = 0;
        for (int i = 0; i < EE; i++) { sBase[i] = acc; acc += sNT[i]; }
    }
    __syncthreads();
    int base = sBase[e];
    for (int i = 0; i < nt; i++) g_tiles[base + i] = make_int2(e, i * 32);
}

// ---------------- GEMM A: act = silu(x@w1) * (x@w3), grouped per expert ----------------
// BM=32, BN=64, BK=16; 256 threads; thread tile 2m x 4n over two output matrices
__global__ __launch_bounds__(256) void k_gemmA(const float* __restrict__ x,
                                               const float* __restrict__ w1,
                                               const float* __restrict__ w3) {
    int2 tile = g_tiles[blockIdx.x];
    int e = tile.x;
    if (e < 0) return;
    int m0 = tile.y;
    int cnt = g_counts[e];
    int n0 = blockIdx.y * 64;

    __shared__ float Xs[16][33];     // [k][m]
    __shared__ float W1s[16][68];    // [k][n]
    __shared__ float W3s[16][68];
    __shared__ int sPair[32];

    const int tid = threadIdx.x;
    if (tid < 32) {
        int idx = m0 + tid;
        sPair[tid] = (idx < cnt) ? g_list[e * TT + idx] : -1;
    }
    __syncthreads();

    const int tx = tid & 15, ty = tid >> 4;
    const float* w1e = w1 + (size_t)e * HH * DD;
    const float* w3e = w3 + (size_t)e * HH * DD;

    // A-load mapping: threads 0..127, 4 threads per row, float4 each
    const int am = tid >> 2;             // 0..31 row (for tid<128)
    const int ak4 = (tid & 3) * 4;       // k offset
    // B-load mapping: k = tid>>4, n4 = (tid&15)*4
    const int bk = tid >> 4;
    const int bn4 = (tid & 15) * 4;

    float acc1[2][4], acc3[2][4];
#pragma unroll
    for (int i = 0; i < 2; i++)
#pragma unroll
        for (int j = 0; j < 4; j++) { acc1[i][j] = 0.f; acc3[i][j] = 0.f; }

    for (int k0 = 0; k0 < HH; k0 += 16) {
        if (tid < 128) {
            int p = sPair[am];
            float4 v = make_float4(0.f, 0.f, 0.f, 0.f);
            if (p >= 0) v = *(const float4*)(x + (size_t)(p >> 1) * HH + k0 + ak4);
            Xs[ak4 + 0][am] = v.x; Xs[ak4 + 1][am] = v.y;
            Xs[ak4 + 2][am] = v.z; Xs[ak4 + 3][am] = v.w;
        }
        {
            size_t off = (size_t)(k0 + bk) * DD + n0 + bn4;
            *(float4*)&W1s[bk][bn4] = *(const float4*)(w1e + off);
            *(float4*)&W3s[bk][bn4] = *(const float4*)(w3e + off);
        }
        __syncthreads();
#pragma unroll
        for (int kk = 0; kk < 16; kk++) {
            float a0 = Xs[kk][ty * 2 + 0];
            float a1 = Xs[kk][ty * 2 + 1];
            float4 b1 = *(float4*)&W1s[kk][tx * 4];
            float4 b3 = *(float4*)&W3s[kk][tx * 4];
            acc1[0][0] += a0 * b1.x; acc1[0][1] += a0 * b1.y; acc1[0][2] += a0 * b1.z; acc1[0][3] += a0 * b1.w;
            acc1[1][0] += a1 * b1.x; acc1[1][1] += a1 * b1.y; acc1[1][2] += a1 * b1.z; acc1[1][3] += a1 * b1.w;
            acc3[0][0] += a0 * b3.x; acc3[0][1] += a0 * b3.y; acc3[0][2] += a0 * b3.z; acc3[0][3] += a0 * b3.w;
            acc3[1][0] += a1 * b3.x; acc3[1][1] += a1 * b3.y; acc3[1][2] += a1 * b3.z; acc3[1][3] += a1 * b3.w;
        }
        __syncthreads();
    }

#pragma unroll
    for (int mi = 0; mi < 2; mi++) {
        int m = ty * 2 + mi;
        int p = sPair[m];
        if (p >= 0) {
            float4 o;
            { float h = acc1[mi][0], g = acc3[mi][0]; o.x = h * g / (1.f + __expf(-h)); }
            { float h = acc1[mi][1], g = acc3[mi][1]; o.y = h * g / (1.f + __expf(-h)); }
            { float h = acc1[mi][2], g = acc3[mi][2]; o.z = h * g / (1.f + __expf(-h)); }
            { float h = acc1[mi][3], g = acc3[mi][3]; o.w = h * g / (1.f + __expf(-h)); }
            *(float4*)(g_act + (size_t)p * DD + n0 + tx * 4) = o;
        }
    }
}

// ---------------- GEMM B: out += cw * (act @ w2), grouped per expert ----------------
// BM=32, BN=128, BK=16; 256 threads; thread tile 2m x 8n
__global__ __launch_bounds__(256) void k_gemmB(const float* __restrict__ w2,
                                               float* __restrict__ out) {
    int2 tile = g_tiles[blockIdx.x];
    int e = tile.x;
    if (e < 0) return;
    int m0 = tile.y;
    int cnt = g_counts[e];
    int n0 = blockIdx.y * 128;

    __shared__ float As[16][33];     // [k][m]
    __shared__ float Bs[16][132];    // [k][n]
    __shared__ int sPair[32];
    __shared__ float sW[32];

    const int tid = threadIdx.x;
    if (tid < 32) {
        int idx = m0 + tid;
        int p = (idx < cnt) ? g_list[e * TT + idx] : -1;
        sPair[tid] = p;
        sW[tid] = (p >= 0) ? g_topk_w[p] : 0.f;
    }
    __syncthreads();

    const int tx = tid & 15, ty = tid >> 4;
    const float* w2e = w2 + (size_t)e * DD * HH;

    const int am = tid >> 2;
    const int ak4 = (tid & 3) * 4;
    const int bk = tid >> 4;
    const int bn8 = (tid & 15) * 8;

    float acc[2][8];
#pragma unroll
    for (int i = 0; i < 2; i++)
#pragma unroll
        for (int j = 0; j < 8; j++) acc[i][j] = 0.f;

    for (int k0 = 0; k0 < DD; k0 += 16) {
        if (tid < 128) {
            int p = sPair[am];
            float4 v = make_float4(0.f, 0.f, 0.f, 0.f);
            if (p >= 0) v = *(const float4*)(g_act + (size_t)p * DD + k0 + ak4);
            As[ak4 + 0][am] = v.x; As[ak4 + 1][am] = v.y;
            As[ak4 + 2][am] = v.z; As[ak4 + 3][am] = v.w;
        }
        {
            size_t off = (size_t)(k0 + bk) * HH + n0 + bn8;
            *(float4*)&Bs[bk][bn8 + 0] = *(const float4*)(w2e + off);
            *(float4*)&Bs[bk][bn8 + 4] = *(const float4*)(w2e + off + 4);
        }
        __syncthreads();
#pragma unroll
        for (int kk = 0; kk < 16; kk++) {
            float a0 = As[kk][ty * 2 + 0];
            float a1 = As[kk][ty * 2 + 1];
            float4 bl = *(float4*)&Bs[kk][tx * 8 + 0];
            float4 bh = *(float4*)&Bs[kk][tx * 8 + 4];
            acc[0][0] += a0 * bl.x; acc[0][1] += a0 * bl.y; acc[0][2] += a0 * bl.z; acc[0][3] += a0 * bl.w;
            acc[0][4] += a0 * bh.x; acc[0][5] += a0 * bh.y; acc[0][6] += a0 * bh.z; acc[0][7] += a0 * bh.w;
            acc[1][0] += a1 * bl.x; acc[1][1] += a1 * bl.y; acc[1][2] += a1 * bl.z; acc[1][3] += a1 * bl.w;
            acc[1][4] += a1 * bh.x; acc[1][5] += a1 * bh.y; acc[1][6] += a1 * bh.z; acc[1][7] += a1 * bh.w;
        }
        __syncthreads();
    }

#pragma unroll
    for (int mi = 0; mi < 2; mi++) {
        int m = ty * 2 + mi;
        int p = sPair[m];
        if (p >= 0) {
            int t = p >> 1;
            float wgt = sW[m];
            float* dst = out + (size_t)t * HH + n0 + tx * 8;
#pragma unroll
            for (int j = 0; j < 8; j++) atomicAdd(dst + j, acc[mi][j] * wgt);
        }
    }
}

// ---------------- launch ----------------
extern "C" void kernel_launch(void* const* d_in, const int* in_sizes, int n_in,
                              void* d_out, int out_size) {
    const float* x    = (const float*)d_in[0];
    const float* w1   = (const float*)d_in[1];
    const float* w3   = (const float*)d_in[2];
    const float* w2   = (const float*)d_in[3];
    const float* gate = (const float*)d_in[4];
    float* out = (float*)d_out;

    k_zero<<<512, 256>>>(out);
    k_router<<<64, 256>>>(x, gate);
    k_build_lists<<<8, 256>>>();
    k_build_tiles<<<1, 64>>>();
    k_gemmA<<<dim3(NTILES, 8), 256>>>(x, w1, w3);
    k_gemmB<<<dim3(NTILES, 8), 256>>>(w2, out);
    if (out_size > TT * HH) {
        k_lb<<<1, 64>>>(out + TT * HH);
    }
}

// round 4
// speedup vs baseline: 1.4150x; 1.4150x over previous
#include <cuda_runtime.h>
#include <math.h>
#include <stdint.h>

#define TT 2048
#define HH 1024
#define DD 512
#define EE 64
#define TOPK 2
#define NTILES 128   // sum ceil(cnt_e/64) <= 127 always

// ---------------- scratch (device globals; no allocation allowed) ----------------
__device__ int   g_topk_i[TT * TOPK];
__device__ float g_topk_w[TT * TOPK];
__device__ int   g_counts[EE];
__device__ int   g_list[EE * TT];              // pairid = t*2+k entries, grouped by expert
__device__ float g_act[TT * TOPK * DD];        // 8 MB activation scratch
__device__ float g_usage_partial[64 * EE];     // [router_block][expert]
__device__ int2  g_tiles[NTILES];              // {expert, m0}; -1-padded

// ---------------- zero out + counts ----------------
__global__ void k_zero(float* __restrict__ out) {
    int i = blockIdx.x * blockDim.x + threadIdx.x;
    int stride = gridDim.x * blockDim.x;
    for (int j = i; j < TT * HH; j += stride) out[j] = 0.f;
    if (i < EE) g_counts[i] = 0;
}

// ---------------- router: logits GEMM + top2 + softmax stats ----------------
__global__ __launch_bounds__(256) void k_router(const float* __restrict__ x,
                                                const float* __restrict__ gate) {
    __shared__ float Xs[32][33];
    __shared__ float Gs[32][68];
    __shared__ float Ls[32][65];
    __shared__ float sM[32], sInv[32];

    const int t0 = blockIdx.x * 32;
    const int tid = threadIdx.x;
    const int tx = tid & 15, ty = tid >> 4;

    float acc[2][4];
#pragma unroll
    for (int i = 0; i < 2; i++)
#pragma unroll
        for (int j = 0; j < 4; j++) acc[i][j] = 0.f;

    for (int k0 = 0; k0 < HH; k0 += 32) {
        {
            int m = tid >> 3, k4 = (tid & 7) * 4;
            float4 v = *(const float4*)(x + (size_t)(t0 + m) * HH + k0 + k4);
            Xs[m][k4 + 0] = v.x; Xs[m][k4 + 1] = v.y;
            Xs[m][k4 + 2] = v.z; Xs[m][k4 + 3] = v.w;
        }
        {
            int k = tid >> 4, j4 = (tid & 15) * 4;
#pragma unroll
            for (int r = 0; r < 2; r++) {
                float4 v = *(const float4*)(gate + (size_t)(k0 + k + r * 16) * EE + j4);
                *(float4*)&Gs[k + r * 16][j4] = v;
            }
        }
        __syncthreads();
#pragma unroll
        for (int kk = 0; kk < 32; kk++) {
            float a0 = Xs[ty * 2 + 0][kk];
            float a1 = Xs[ty * 2 + 1][kk];
            float4 b = *(float4*)&Gs[kk][tx * 4];
            acc[0][0] += a0 * b.x; acc[0][1] += a0 * b.y; acc[0][2] += a0 * b.z; acc[0][3] += a0 * b.w;
            acc[1][0] += a1 * b.x; acc[1][1] += a1 * b.y; acc[1][2] += a1 * b.z; acc[1][3] += a1 * b.w;
        }
        __syncthreads();
    }
#pragma unroll
    for (int mi = 0; mi < 2; mi++)
#pragma unroll
        for (int ni = 0; ni < 4; ni++)
            Ls[ty * 2 + mi][tx * 4 + ni] = acc[mi][ni];
    __syncthreads();

    if (tid < 32) {
        int t = t0 + tid;
        float m1 = -1e30f, m2 = -1e30f;
        int i1 = -1, i2 = -1;
        for (int e = 0; e < EE; e++) {
            float l = Ls[tid][e];
            if (l > m1) { m2 = m1; i2 = i1; m1 = l; i1 = e; }
            else if (l > m2) { m2 = l; i2 = e; }
        }
        float den = 0.f;
        for (int e = 0; e < EE; e++) den += __expf(Ls[tid][e] - m1);
        sM[tid] = m1; sInv[tid] = 1.f / den;
        float e2 = __expf(m2 - m1);
        float s = 1.f + e2;
        g_topk_i[t * 2 + 0] = i1;
        g_topk_i[t * 2 + 1] = i2;
        g_topk_w[t * 2 + 0] = 1.f / s;
        g_topk_w[t * 2 + 1] = e2 / s;
    }
    __syncthreads();

    if (tid < EE) {
        float s = 0.f;
        for (int r = 0; r < 32; r++)
            s += __expf(Ls[r][tid] - sM[r]) * sInv[r];
        g_usage_partial[blockIdx.x * EE + tid] = s;
    }
}

// ---------------- lb loss ----------------
__global__ void k_lb(float* __restrict__ out_lb) {
    __shared__ float red[64];
    int e = threadIdx.x;
    float s = 0.f;
    for (int b = 0; b < 64; b++) s += g_usage_partial[b * EE + e];
    float u = s / (float)TT;
    red[e] = u * u;
    __syncthreads();
    for (int off = 32; off > 0; off >>= 1) {
        if (e < off) red[e] += red[e + off];
        __syncthreads();
    }
    if (e == 0) *out_lb = (float)EE * red[0];
}

// ---------------- build per-expert token lists ----------------
__global__ void k_build_lists() {
    int t = blockIdx.x * blockDim.x + threadIdx.x;
    if (t < TT) {
#pragma unroll
        for (int k = 0; k < TOPK; k++) {
            int e = g_topk_i[t * 2 + k];
            int pos = atomicAdd(&g_counts[e], 1);
            g_list[e * TT + pos] = t * 2 + k;
        }
    }
}

// ---------------- build tile list (parallel; BM=64) ----------------
__global__ void k_build_tiles() {
    __shared__ int sNT[EE];
    __shared__ int sBase[EE];
    int e = threadIdx.x;  // 64 threads
    for (int i = e; i < NTILES; i += 64) g_tiles[i] = make_int2(-1, 0);
    int nt = (g_counts[e] + 63) >> 6;
    sNT[e] = nt;
    __syncthreads();
    if (e == 0) {
        int acc = 0;
        for (int i = 0; i < EE; i++) { sBase[i] = acc; acc += sNT[i]; }
    }
    __syncthreads();
    int base = sBase[e];
    for (int i = 0; i < nt; i++) g_tiles[base + i] = make_int2(e, i * 64);
}

// ---------------- GEMM A: act = silu(x@w1) * (x@w3) ----------------
// BM=64, BN=64, BK=32; 256 threads; thread tile 4m x 4n over TWO output matrices
__global__ __launch_bounds__(256, 2) void k_gemmA(const float* __restrict__ x,
                                                  const float* __restrict__ w1,
                                                  const float* __restrict__ w3) {
    int2 tile = g_tiles[blockIdx.x];
    int e = tile.x;
    if (e < 0) return;
    int m0 = tile.y;
    int cnt = g_counts[e];
    int n0 = blockIdx.y * 64;

    __shared__ float Xs[32][68];     // [k][m]
    __shared__ float W1s[32][68];    // [k][n]
    __shared__ float W3s[32][68];
    __shared__ int sPair[64];

    const int tid = threadIdx.x;
    if (tid < 64) {
        int idx = m0 + tid;
        sPair[tid] = (idx < cnt) ? g_list[e * TT + idx] : -1;
    }
    __syncthreads();

    const int tx = tid & 15, ty = tid >> 4;
    const float* w1e = w1 + (size_t)e * HH * DD;
    const float* w3e = w3 + (size_t)e * HH * DD;

    // A-load: m = tid>>2 (0..63), 2 float4 at k = (tid&3)*8 (+0,+4)
    const int am = tid >> 2;
    const int akb = (tid & 3) * 8;
    const int ap = sPair[am];
    const float* arow = (ap >= 0) ? (x + (size_t)(ap >> 1) * HH) : 0;
    // B-load: k = tid>>3 (0..31), 2 float4 at n = (tid&7)*8 (+0,+4)
    const int bk = tid >> 3;
    const int bnb = (tid & 7) * 8;

    float acc1[4][4], acc3[4][4];
#pragma unroll
    for (int i = 0; i < 4; i++)
#pragma unroll
        for (int j = 0; j < 4; j++) { acc1[i][j] = 0.f; acc3[i][j] = 0.f; }

    for (int k0 = 0; k0 < HH; k0 += 32) {
#pragma unroll
        for (int r = 0; r < 2; r++) {
            int k4 = akb + r * 4;
            float4 v = make_float4(0.f, 0.f, 0.f, 0.f);
            if (ap >= 0) v = *(const float4*)(arow + k0 + k4);
            Xs[k4 + 0][am] = v.x; Xs[k4 + 1][am] = v.y;
            Xs[k4 + 2][am] = v.z; Xs[k4 + 3][am] = v.w;
        }
        {
            size_t off = (size_t)(k0 + bk) * DD + n0 + bnb;
            *(float4*)&W1s[bk][bnb + 0] = *(const float4*)(w1e + off);
            *(float4*)&W1s[bk][bnb + 4] = *(const float4*)(w1e + off + 4);
            *(float4*)&W3s[bk][bnb + 0] = *(const float4*)(w3e + off);
            *(float4*)&W3s[bk][bnb + 4] = *(const float4*)(w3e + off + 4);
        }
        __syncthreads();
#pragma unroll
        for (int kk = 0; kk < 32; kk++) {
            float4 a  = *(float4*)&Xs[kk][ty * 4];
            float4 b1 = *(float4*)&W1s[kk][tx * 4];
            float4 b3 = *(float4*)&W3s[kk][tx * 4];
            float av[4] = {a.x, a.y, a.z, a.w};
#pragma unroll
            for (int i = 0; i < 4; i++) {
                acc1[i][0] += av[i] * b1.x; acc1[i][1] += av[i] * b1.y;
                acc1[i][2] += av[i] * b1.z; acc1[i][3] += av[i] * b1.w;
                acc3[i][0] += av[i] * b3.x; acc3[i][1] += av[i] * b3.y;
                acc3[i][2] += av[i] * b3.z; acc3[i][3] += av[i] * b3.w;
            }
        }
        __syncthreads();
    }

#pragma unroll
    for (int mi = 0; mi < 4; mi++) {
        int m = ty * 4 + mi;
        int p = sPair[m];
        if (p >= 0) {
            float4 o;
            { float h = acc1[mi][0], g = acc3[mi][0]; o.x = h * g / (1.f + __expf(-h)); }
            { float h = acc1[mi][1], g = acc3[mi][1]; o.y = h * g / (1.f + __expf(-h)); }
            { float h = acc1[mi][2], g = acc3[mi][2]; o.z = h * g / (1.f + __expf(-h)); }
            { float h = acc1[mi][3], g = acc3[mi][3]; o.w = h * g / (1.f + __expf(-h)); }
            *(float4*)(g_act + (size_t)p * DD + n0 + tx * 4) = o;
        }
    }
}

// ---------------- GEMM B: out += cw * (act @ w2) ----------------
// BM=64, BN=128, BK=32; 256 threads; thread tile 4m x 8n
__global__ __launch_bounds__(256, 2) void k_gemmB(const float* __restrict__ w2,
                                                  float* __restrict__ out) {
    int2 tile = g_tiles[blockIdx.x];
    int e = tile.x;
    if (e < 0) return;
    int m0 = tile.y;
    int cnt = g_counts[e];
    int n0 = blockIdx.y * 128;

    __shared__ float As[32][68];     // [k][m]
    __shared__ float Bs[32][132];    // [k][n]
    __shared__ int sPair[64];
    __shared__ float sW[64];

    const int tid = threadIdx.x;
    if (tid < 64) {
        int idx = m0 + tid;
        int p = (idx < cnt) ? g_list[e * TT + idx] : -1;
        sPair[tid] = p;
        sW[tid] = (p >= 0) ? g_topk_w[p] : 0.f;
    }
    __syncthreads();

    const int tx = tid & 15, ty = tid >> 4;
    const float* w2e = w2 + (size_t)e * DD * HH;

    const int am = tid >> 2;
    const int akb = (tid & 3) * 8;
    const int ap = sPair[am];
    const float* arow = (ap >= 0) ? (g_act + (size_t)ap * DD) : 0;
    const int bk = tid >> 3;
    const int bnb = (tid & 7) * 16;

    float acc[4][8];
#pragma unroll
    for (int i = 0; i < 4; i++)
#pragma unroll
        for (int j = 0; j < 8; j++) acc[i][j] = 0.f;

    for (int k0 = 0; k0 < DD; k0 += 32) {
#pragma unroll
        for (int r = 0; r < 2; r++) {
            int k4 = akb + r * 4;
            float4 v = make_float4(0.f, 0.f, 0.f, 0.f);
            if (ap >= 0) v = *(const float4*)(arow + k0 + k4);
            As[k4 + 0][am] = v.x; As[k4 + 1][am] = v.y;
            As[k4 + 2][am] = v.z; As[k4 + 3][am] = v.w;
        }
        {
            size_t off = (size_t)(k0 + bk) * HH + n0 + bnb;
#pragma unroll
            for (int r = 0; r < 4; r++)
                *(float4*)&Bs[bk][bnb + r * 4] = *(const float4*)(w2e + off + r * 4);
        }
        __syncthreads();
#pragma unroll
        for (int kk = 0; kk < 32; kk++) {
            float4 a  = *(float4*)&As[kk][ty * 4];
            float4 bl = *(float4*)&Bs[kk][tx * 8 + 0];
            float4 bh = *(float4*)&Bs[kk][tx * 8 + 4];
            float av[4] = {a.x, a.y, a.z, a.w};
#pragma unroll
            for (int i = 0; i < 4; i++) {
                acc[i][0] += av[i] * bl.x; acc[i][1] += av[i] * bl.y;
                acc[i][2] += av[i] * bl.z; acc[i][3] += av[i] * bl.w;
                acc[i][4] += av[i] * bh.x; acc[i][5] += av[i] * bh.y;
                acc[i][6] += av[i] * bh.z; acc[i][7] += av[i] * bh.w;
            }
        }
        __syncthreads();
    }

#pragma unroll
    for (int mi = 0; mi < 4; mi++) {
        int m = ty * 4 + mi;
        int p = sPair[m];
        if (p >= 0) {
            int t = p >> 1;
            float wgt = sW[m];
            float* dst = out + (size_t)t * HH + n0 + tx * 8;
#pragma unroll
            for (int j = 0; j < 8; j++) atomicAdd(dst + j, acc[mi][j] * wgt);
        }
    }
}

// ---------------- launch ----------------
extern "C" void kernel_launch(void* const* d_in, const int* in_sizes, int n_in,
                              void* d_out, int out_size) {
    const float* x    = (const float*)d_in[0];
    const float* w1   = (const float*)d_in[1];
    const float* w3   = (const float*)d_in[2];
    const float* w2   = (const float*)d_in[3];
    const float* gate = (const float*)d_in[4];
    float* out = (float*)d_out;

    k_zero<<<512, 256>>>(out);
    k_router<<<64, 256>>>(x, gate);
    k_build_lists<<<8, 256>>>();
    k_build_tiles<<<1, 64>>>();
    k_gemmA<<<dim3(NTILES, 8), 256>>>(x, w1, w3);
    k_gemmB<<<dim3(NTILES, 8), 256>>>(w2, out);
    if (out_size > TT * HH) {
        k_lb<<<1, 64>>>(out + TT * HH);
    }
}

// round 6
// speedup vs baseline: 2.5234x; 1.7833x over previous
#include <cuda_runtime.h>
#include <cuda_bf16.h>
#include <math.h>
#include <stdint.h>

#define TT 2048
#define HH 1024
#define DD 512
#define EE 64
#define TOPK 2
#define NTILES 128   // sum ceil(cnt_e/64) <= 127 always

// ---------------- scratch ----------------
__device__ int   g_topk_i[TT * TOPK];
__device__ float g_topk_w[TT * TOPK];
__device__ int   g_counts[EE];
__device__ int   g_list[EE * TT];
__device__ float g_usage_partial[64 * EE];
__device__ int2  g_tiles[NTILES];
__device__ __nv_bfloat16 g_xh[TT * HH], g_xl[TT * HH];               // split x
__device__ __nv_bfloat16 g_ah[TT * TOPK * DD], g_al[TT * TOPK * DD]; // split act

// ---------------- helpers ----------------
__device__ __forceinline__ uint32_t pack_bf2(__nv_bfloat16 a, __nv_bfloat16 b) {
    return (uint32_t)__bfloat16_as_ushort(a) | ((uint32_t)__bfloat16_as_ushort(b) << 16);
}
__device__ __forceinline__ void split32(float v, __nv_bfloat16& h, __nv_bfloat16& l) {
    h = __float2bfloat16(v);
    l = __float2bfloat16(v - __bfloat162float(h));
}
// D(16x8,f32) += A(16x16,bf16) * B(16x8,bf16); row.col
__device__ __forceinline__ void mma16816(float* d, const uint32_t* a, const uint32_t* b) {
    asm volatile("mma.sync.aligned.m16n8k16.row.col.f32.bf16.bf16.f32 "
        "{%0,%1,%2,%3}, {%4,%5,%6,%7}, {%8,%9}, {%0,%1,%2,%3};"
        : "+f"(d[0]), "+f"(d[1]), "+f"(d[2]), "+f"(d[3])
        : "r"(a[0]), "r"(a[1]), "r"(a[2]), "r"(a[3]), "r"(b[0]), "r"(b[1]));
}

// ---------------- zero out + counts ----------------
__global__ void k_zero(float* __restrict__ out) {
    int i = blockIdx.x * blockDim.x + threadIdx.x;
    int stride = gridDim.x * blockDim.x;
    for (int j = i; j < TT * HH; j += stride) out[j] = 0.f;
    if (i < EE) g_counts[i] = 0;
}

// ---------------- split x into bf16 hi/lo ----------------
__global__ void k_cvt_x(const float* __restrict__ x) {
    int i = blockIdx.x * blockDim.x + threadIdx.x;   // over TT*HH/4
    float4 v = ((const float4*)x)[i];
    __nv_bfloat16 h0, h1, h2, h3, l0, l1, l2, l3;
    split32(v.x, h0, l0); split32(v.y, h1, l1);
    split32(v.z, h2, l2); split32(v.w, h3, l3);
    uint2 ph, pl;
    ph.x = pack_bf2(h0, h1); ph.y = pack_bf2(h2, h3);
    pl.x = pack_bf2(l0, l1); pl.y = pack_bf2(l2, l3);
    ((uint2*)g_xh)[i] = ph;
    ((uint2*)g_xl)[i] = pl;
}

// ---------------- router (fp32 SIMT; small) ----------------
__global__ __launch_bounds__(256) void k_router(const float* __restrict__ x,
                                                const float* __restrict__ gate) {
    __shared__ float Xs[32][33];
    __shared__ float Gs[32][68];
    __shared__ float Ls[32][65];
    __shared__ float sM[32], sInv[32];

    const int t0 = blockIdx.x * 32;
    const int tid = threadIdx.x;
    const int tx = tid & 15, ty = tid >> 4;

    float acc[2][4];
#pragma unroll
    for (int i = 0; i < 2; i++)
#pragma unroll
        for (int j = 0; j < 4; j++) acc[i][j] = 0.f;

    for (int k0 = 0; k0 < HH; k0 += 32) {
        {
            int m = tid >> 3, k4 = (tid & 7) * 4;
            float4 v = *(const float4*)(x + (size_t)(t0 + m) * HH + k0 + k4);
            Xs[m][k4 + 0] = v.x; Xs[m][k4 + 1] = v.y;
            Xs[m][k4 + 2] = v.z; Xs[m][k4 + 3] = v.w;
        }
        {
            int k = tid >> 4, j4 = (tid & 15) * 4;
#pragma unroll
            for (int r = 0; r < 2; r++) {
                float4 v = *(const float4*)(gate + (size_t)(k0 + k + r * 16) * EE + j4);
                *(float4*)&Gs[k + r * 16][j4] = v;
            }
        }
        __syncthreads();
#pragma unroll
        for (int kk = 0; kk < 32; kk++) {
            float a0 = Xs[ty * 2 + 0][kk];
            float a1 = Xs[ty * 2 + 1][kk];
            float4 b = *(float4*)&Gs[kk][tx * 4];
            acc[0][0] += a0 * b.x; acc[0][1] += a0 * b.y; acc[0][2] += a0 * b.z; acc[0][3] += a0 * b.w;
            acc[1][0] += a1 * b.x; acc[1][1] += a1 * b.y; acc[1][2] += a1 * b.z; acc[1][3] += a1 * b.w;
        }
        __syncthreads();
    }
#pragma unroll
    for (int mi = 0; mi < 2; mi++)
#pragma unroll
        for (int ni = 0; ni < 4; ni++)
            Ls[ty * 2 + mi][tx * 4 + ni] = acc[mi][ni];
    __syncthreads();

    if (tid < 32) {
        int t = t0 + tid;
        float m1 = -1e30f, m2 = -1e30f;
        int i1 = -1, i2 = -1;
        for (int e = 0; e < EE; e++) {
            float l = Ls[tid][e];
            if (l > m1) { m2 = m1; i2 = i1; m1 = l; i1 = e; }
            else if (l > m2) { m2 = l; i2 = e; }
        }
        float den = 0.f;
        for (int e = 0; e < EE; e++) den += __expf(Ls[tid][e] - m1);
        sM[tid] = m1; sInv[tid] = 1.f / den;
        float e2 = __expf(m2 - m1);
        float s = 1.f + e2;
        g_topk_i[t * 2 + 0] = i1;
        g_topk_i[t * 2 + 1] = i2;
        g_topk_w[t * 2 + 0] = 1.f / s;
        g_topk_w[t * 2 + 1] = e2 / s;
    }
    __syncthreads();

    if (tid < EE) {
        float s = 0.f;
        for (int r = 0; r < 32; r++)
            s += __expf(Ls[r][tid] - sM[r]) * sInv[r];
        g_usage_partial[blockIdx.x * EE + tid] = s;
    }
}

__global__ void k_lb(float* __restrict__ out_lb) {
    __shared__ float red[64];
    int e = threadIdx.x;
    float s = 0.f;
    for (int b = 0; b < 64; b++) s += g_usage_partial[b * EE + e];
    float u = s / (float)TT;
    red[e] = u * u;
    __syncthreads();
    for (int off = 32; off > 0; off >>= 1) {
        if (e < off) red[e] += red[e + off];
        __syncthreads();
    }
    if (e == 0) *out_lb = (float)EE * red[0];
}

__global__ void k_build_lists() {
    int t = blockIdx.x * blockDim.x + threadIdx.x;
    if (t < TT) {
#pragma unroll
        for (int k = 0; k < TOPK; k++) {
            int e = g_topk_i[t * 2 + k];
            int pos = atomicAdd(&g_counts[e], 1);
            g_list[e * TT + pos] = t * 2 + k;
        }
    }
}

__global__ void k_build_tiles() {
    __shared__ int sNT[EE];
    __shared__ int sBase[EE];
    int e = threadIdx.x;  // 64 threads
    for (int i = e; i < NTILES; i += 64) g_tiles[i] = make_int2(-1, 0);
    int nt = (g_counts[e] + 63) >> 6;
    sNT[e] = nt;
    __syncthreads();
    if (e == 0) {
        int acc = 0;
        for (int i = 0; i < EE; i++) { sBase[i] = acc; acc += sNT[i]; }
    }
    __syncthreads();
    int base = sBase[e];
    for (int i = 0; i < nt; i++) g_tiles[base + i] = make_int2(e, i * 64);
}

// ================= GEMM A (mma.sync): act = silu(x@w1)*(x@w3), split-bf16 =================
// Block: 64 pairs (M) x 64 d (N); K-chunk 32. 8 warps as 2m x 4n; warp tile 32x16.
// SMEM u32 = bf16x2 k-pairs, row stride 17 (conflict-free).
__global__ __launch_bounds__(256, 2) void k_gemmA(const float* __restrict__ w1,
                                                  const float* __restrict__ w3) {
    __shared__ uint32_t XSh[64][17], XSl[64][17];
    __shared__ uint32_t W1h[64][17], W1l[64][17], W3h[64][17], W3l[64][17];
    __shared__ int sPair[64];

    int2 tile = g_tiles[blockIdx.x];
    if (tile.x < 0) return;
    const int e = tile.x, t0 = tile.y;
    const int d0 = blockIdx.y * 64;
    const int tid = threadIdx.x;
    const int lane = tid & 31, wid = tid >> 5;
    const int g = lane >> 2, q = lane & 3;
    const int warp_m = wid & 1, warp_n = wid >> 1;
    const int cnt = g_counts[e];

    if (tid < 64) {
        int idx = t0 + tid;
        sPair[tid] = (idx < cnt) ? g_list[e * TT + idx] : -1;
    }
    __syncthreads();

    const float* w1e = w1 + (size_t)e * HH * DD;
    const float* w3e = w3 + (size_t)e * HH * DD;

    // X staging: row = tid>>2, 4 consecutive kpairs at (tid&3)*4
    const int xrow = tid >> 2, xkp = (tid & 3) * 4;
    const int xp = sPair[xrow];
    const __nv_bfloat16* xsh = (xp >= 0) ? (g_xh + (size_t)(xp >> 1) * HH + xkp * 2) : 0;
    const __nv_bfloat16* xsl = (xp >= 0) ? (g_xl + (size_t)(xp >> 1) * HH + xkp * 2) : 0;
    // W staging: dd = tid&63, k-quarter = tid>>6
    const int dd = tid & 63, q4 = tid >> 6;

    float acc1[2][2][4], acc3[2][2][4];
#pragma unroll
    for (int a = 0; a < 2; a++)
#pragma unroll
        for (int b = 0; b < 2; b++)
#pragma unroll
            for (int c = 0; c < 4; c++) { acc1[a][b][c] = 0.f; acc3[a][b][c] = 0.f; }

    for (int k0 = 0; k0 < HH; k0 += 32) {
        __syncthreads();
        // stage X (hi/lo)
        {
            uint4 vh = make_uint4(0, 0, 0, 0), vl = make_uint4(0, 0, 0, 0);
            if (xp >= 0) {
                vh = *(const uint4*)(xsh + k0);
                vl = *(const uint4*)(xsl + k0);
            }
            XSh[xrow][xkp + 0] = vh.x; XSh[xrow][xkp + 1] = vh.y;
            XSh[xrow][xkp + 2] = vh.z; XSh[xrow][xkp + 3] = vh.w;
            XSl[xrow][xkp + 0] = vl.x; XSl[xrow][xkp + 1] = vl.y;
            XSl[xrow][xkp + 2] = vl.z; XSl[xrow][xkp + 3] = vl.w;
        }
        // stage W1/W3 (split on the fly); k rows q4*8..q4*8+7
        {
            const float* p1 = w1e + (size_t)(k0 + q4 * 8) * DD + d0 + dd;
            const float* p3 = w3e + (size_t)(k0 + q4 * 8) * DD + d0 + dd;
#pragma unroll
            for (int i = 0; i < 4; i++) {
                float a0 = p1[(2 * i) * DD], a1 = p1[(2 * i + 1) * DD];
                float c0 = p3[(2 * i) * DD], c1 = p3[(2 * i + 1) * DD];
                __nv_bfloat16 h0, h1, l0, l1;
                split32(a0, h0, l0); split32(a1, h1, l1);
                W1h[dd][q4 * 4 + i] = pack_bf2(h0, h1);
                W1l[dd][q4 * 4 + i] = pack_bf2(l0, l1);
                split32(c0, h0, l0); split32(c1, h1, l1);
                W3h[dd][q4 * 4 + i] = pack_bf2(h0, h1);
                W3l[dd][q4 * 4 + i] = pack_bf2(l0, l1);
            }
        }
        __syncthreads();

#pragma unroll
        for (int s = 0; s < 2; s++) {
            const int s8 = s * 8;
            uint32_t ah[2][4], al[2][4];
#pragma unroll
            for (int mf = 0; mf < 2; mf++) {
                int r0 = warp_m * 32 + mf * 16 + g;
                ah[mf][0] = XSh[r0][s8 + q];     ah[mf][1] = XSh[r0 + 8][s8 + q];
                ah[mf][2] = XSh[r0][s8 + 4 + q]; ah[mf][3] = XSh[r0 + 8][s8 + 4 + q];
                al[mf][0] = XSl[r0][s8 + q];     al[mf][1] = XSl[r0 + 8][s8 + q];
                al[mf][2] = XSl[r0][s8 + 4 + q]; al[mf][3] = XSl[r0 + 8][s8 + 4 + q];
            }
#pragma unroll
            for (int nf = 0; nf < 2; nf++) {
                int n = warp_n * 16 + nf * 8 + g;
                uint32_t b1h[2] = { W1h[n][s8 + q], W1h[n][s8 + 4 + q] };
                uint32_t b1l[2] = { W1l[n][s8 + q], W1l[n][s8 + 4 + q] };
                uint32_t b3h[2] = { W3h[n][s8 + q], W3h[n][s8 + 4 + q] };
                uint32_t b3l[2] = { W3l[n][s8 + q], W3l[n][s8 + 4 + q] };
#pragma unroll
                for (int mf = 0; mf < 2; mf++) {
                    mma16816(acc1[mf][nf], ah[mf], b1h);
                    mma16816(acc1[mf][nf], ah[mf], b1l);
                    mma16816(acc1[mf][nf], al[mf], b1h);
                    mma16816(acc3[mf][nf], ah[mf], b3h);
                    mma16816(acc3[mf][nf], ah[mf], b3l);
                    mma16816(acc3[mf][nf], al[mf], b3h);
                }
            }
        }
    }

    // epilogue: silu(h)*g, split, write act rows directly from fragments
#pragma unroll
    for (int mf = 0; mf < 2; mf++) {
        int rbase = warp_m * 32 + mf * 16 + g;
#pragma unroll
        for (int half = 0; half < 2; half++) {      // c0/c1 vs c2/c3 (row, row+8)
            int r = rbase + half * 8;
            int p = sPair[r];
            if (p < 0) continue;
#pragma unroll
            for (int nf = 0; nf < 2; nf++) {
                int dcol = d0 + warp_n * 16 + nf * 8 + q * 2;
                float h0 = acc1[mf][nf][half * 2 + 0], g0 = acc3[mf][nf][half * 2 + 0];
                float h1 = acc1[mf][nf][half * 2 + 1], g1 = acc3[mf][nf][half * 2 + 1];
                float o0 = h0 * g0 / (1.f + __expf(-h0));
                float o1 = h1 * g1 / (1.f + __expf(-h1));
                __nv_bfloat16 oh0, ol0, oh1, ol1;
                split32(o0, oh0, ol0); split32(o1, oh1, ol1);
                *(uint32_t*)(g_ah + (size_t)p * DD + dcol) = pack_bf2(oh0, oh1);
                *(uint32_t*)(g_al + (size_t)p * DD + dcol) = pack_bf2(ol0, ol1);
            }
        }
    }
}

// ================= GEMM B (mma.sync): out += cw * (act @ w2), split-bf16 =================
// Block: 64 pairs (M) x 128 h (N); K-chunk 32. 8 warps 2m x 4n; warp tile 32x32.
__global__ __launch_bounds__(256, 2) void k_gemmB(const float* __restrict__ w2,
                                                  float* __restrict__ out) {
    __shared__ uint32_t ASh[64][17], ASl[64][17];
    __shared__ uint32_t W2h[128][17], W2l[128][17];
    __shared__ int sPair[64];
    __shared__ float sW[64];

    int2 tile = g_tiles[blockIdx.x];
    if (tile.x < 0) return;
    const int e = tile.x, t0 = tile.y;
    const int h0 = blockIdx.y * 128;
    const int tid = threadIdx.x;
    const int lane = tid & 31, wid = tid >> 5;
    const int g = lane >> 2, q = lane & 3;
    const int warp_m = wid & 1, warp_n = wid >> 1;
    const int cnt = g_counts[e];

    if (tid < 64) {
        int idx = t0 + tid;
        int p = (idx < cnt) ? g_list[e * TT + idx] : -1;
        sPair[tid] = p;
        sW[tid] = (p >= 0) ? g_topk_w[p] : 0.f;
    }
    __syncthreads();

    const float* w2e = w2 + (size_t)e * DD * HH;

    const int xrow = tid >> 2, xkp = (tid & 3) * 4;
    const int xp = sPair[xrow];
    const __nv_bfloat16* ash = (xp >= 0) ? (g_ah + (size_t)xp * DD + xkp * 2) : 0;
    const __nv_bfloat16* asl = (xp >= 0) ? (g_al + (size_t)xp * DD + xkp * 2) : 0;
    const int hh = tid & 127, qh = tid >> 7;   // qh in {0,1}: k halves 0-15 / 16-31

    float acc[2][4][4];
#pragma unroll
    for (int a = 0; a < 2; a++)
#pragma unroll
        for (int b = 0; b < 4; b++)
#pragma unroll
            for (int c = 0; c < 4; c++) acc[a][b][c] = 0.f;

    for (int k0 = 0; k0 < DD; k0 += 32) {
        __syncthreads();
        {
            uint4 vh = make_uint4(0, 0, 0, 0), vl = make_uint4(0, 0, 0, 0);
            if (xp >= 0) {
                vh = *(const uint4*)(ash + k0);
                vl = *(const uint4*)(asl + k0);
            }
            ASh[xrow][xkp + 0] = vh.x; ASh[xrow][xkp + 1] = vh.y;
            ASh[xrow][xkp + 2] = vh.z; ASh[xrow][xkp + 3] = vh.w;
            ASl[xrow][xkp + 0] = vl.x; ASl[xrow][xkp + 1] = vl.y;
            ASl[xrow][xkp + 2] = vl.z; ASl[xrow][xkp + 3] = vl.w;
        }
        {
            const float* p2 = w2e + (size_t)(k0 + qh * 16) * HH + h0 + hh;
#pragma unroll
            for (int i = 0; i < 8; i++) {
                float a0 = p2[(2 * i) * HH], a1 = p2[(2 * i + 1) * HH];
                __nv_bfloat16 hh0, hh1, ll0, ll1;
                split32(a0, hh0, ll0); split32(a1, hh1, ll1);
                W2h[hh][qh * 8 + i] = pack_bf2(hh0, hh1);
                W2l[hh][qh * 8 + i] = pack_bf2(ll0, ll1);
            }
        }
        __syncthreads();

#pragma unroll
        for (int s = 0; s < 2; s++) {
            const int s8 = s * 8;
            uint32_t ah[2][4], al[2][4];
#pragma unroll
            for (int mf = 0; mf < 2; mf++) {
                int r0 = warp_m * 32 + mf * 16 + g;
                ah[mf][0] = ASh[r0][s8 + q];     ah[mf][1] = ASh[r0 + 8][s8 + q];
                ah[mf][2] = ASh[r0][s8 + 4 + q]; ah[mf][3] = ASh[r0 + 8][s8 + 4 + q];
                al[mf][0] = ASl[r0][s8 + q];     al[mf][1] = ASl[r0 + 8][s8 + q];
                al[mf][2] = ASl[r0][s8 + 4 + q]; al[mf][3] = ASl[r0 + 8][s8 + 4 + q];
            }
#pragma unroll
            for (int nf = 0; nf < 4; nf++) {
                int n = warp_n * 32 + nf * 8 + g;
                uint32_t bh[2] = { W2h[n][s8 + q], W2h[n][s8 + 4 + q] };
                uint32_t bl[2] = { W2l[n][s8 + q], W2l[n][s8 + 4 + q] };
#pragma unroll
                for (int mf = 0; mf < 2; mf++) {
                    mma16816(acc[mf][nf], ah[mf], bh);
                    mma16816(acc[mf][nf], ah[mf], bl);
                    mma16816(acc[mf][nf], al[mf], bh);
                }
            }
        }
    }

    // epilogue: scale by cw, atomicAdd directly from fragments
#pragma unroll
    for (int mf = 0; mf < 2; mf++) {
        int rbase = warp_m * 32 + mf * 16 + g;
#pragma unroll
        for (int half = 0; half < 2; half++) {
            int r = rbase + half * 8;
            int p = sPair[r];
            if (p < 0) continue;
            int tok = p >> 1;
            float wgt = sW[r];
            float* orow = out + (size_t)tok * HH;
#pragma unroll
            for (int nf = 0; nf < 4; nf++) {
                int hcol = h0 + warp_n * 32 + nf * 8 + q * 2;
                atomicAdd(orow + hcol + 0, acc[mf][nf][half * 2 + 0] * wgt);
                atomicAdd(orow + hcol + 1, acc[mf][nf][half * 2 + 1] * wgt);
            }
        }
    }
}

// ---------------- launch ----------------
extern "C" void kernel_launch(void* const* d_in, const int* in_sizes, int n_in,
                              void* d_out, int out_size) {
    const float* x    = (const float*)d_in[0];
    const float* w1   = (const float*)d_in[1];
    const float* w3   = (const float*)d_in[2];
    const float* w2   = (const float*)d_in[3];
    const float* gate = (const float*)d_in[4];
    float* out = (float*)d_out;

    k_zero<<<512, 256>>>(out);
    k_router<<<64, 256>>>(x, gate);
    k_build_lists<<<8, 256>>>();
    k_build_tiles<<<1, 64>>>();
    k_cvt_x<<<TT * HH / 4 / 256, 256>>>(x);
    k_gemmA<<<dim3(NTILES, 8), 256>>>(w1, w3);
    k_gemmB<<<dim3(NTILES, 8), 256>>>(w2, out);
    if (out_size > TT * HH) {
        k_lb<<<1, 64>>>(out + TT * HH);
    }
}

// round 7
// speedup vs baseline: 2.8008x; 1.1099x over previous
#include <cuda_runtime.h>
#include <cuda_bf16.h>
#include <math.h>
#include <stdint.h>

#define TT 2048
#define HH 1024
#define DD 512
#define EE 64
#define TOPK 2
#define NTILES 128   // sum ceil(cnt_e/64) <= 127 always

// ---------------- scratch ----------------
__device__ int   g_topk_i[TT * TOPK];
__device__ float g_topk_w[TT * TOPK];
__device__ int   g_counts[EE];
__device__ int   g_list[EE * TT];
__device__ float g_usage_partial[64 * EE];
__device__ int2  g_tiles[NTILES];
__device__ __nv_bfloat16 g_xh[TT * HH], g_xl[TT * HH];               // split x
__device__ __nv_bfloat16 g_ah[TT * TOPK * DD], g_al[TT * TOPK * DD]; // split act

// ---------------- helpers ----------------
__device__ __forceinline__ uint32_t pack_bf2(__nv_bfloat16 a, __nv_bfloat16 b) {
    return (uint32_t)__bfloat16_as_ushort(a) | ((uint32_t)__bfloat16_as_ushort(b) << 16);
}
__device__ __forceinline__ void split32(float v, __nv_bfloat16& h, __nv_bfloat16& l) {
    h = __float2bfloat16(v);
    l = __float2bfloat16(v - __bfloat162float(h));
}
__device__ __forceinline__ void split_pack(float a, float b, uint32_t& hi, uint32_t& lo) {
    __nv_bfloat16 h0, h1, l0, l1;
    split32(a, h0, l0); split32(b, h1, l1);
    hi = pack_bf2(h0, h1); lo = pack_bf2(l0, l1);
}
// D(16x8,f32) += A(16x16,bf16) * B(16x8,bf16); row.col
__device__ __forceinline__ void mma16816(float* d, const uint32_t* a, const uint32_t* b) {
    asm volatile("mma.sync.aligned.m16n8k16.row.col.f32.bf16.bf16.f32 "
        "{%0,%1,%2,%3}, {%4,%5,%6,%7}, {%8,%9}, {%0,%1,%2,%3};"
        : "+f"(d[0]), "+f"(d[1]), "+f"(d[2]), "+f"(d[3])
        : "r"(a[0]), "r"(a[1]), "r"(a[2]), "r"(a[3]), "r"(b[0]), "r"(b[1]));
}

// ---------------- prep: zero out, zero counts, split x ----------------
__global__ void k_prep(const float* __restrict__ x, float* __restrict__ out) {
    int i = blockIdx.x * blockDim.x + threadIdx.x;   // 0 .. TT*HH/4-1
    ((float4*)out)[i] = make_float4(0.f, 0.f, 0.f, 0.f);
    float4 v = ((const float4*)x)[i];
    uint2 ph, pl;
    split_pack(v.x, v.y, ph.x, pl.x);
    split_pack(v.z, v.w, ph.y, pl.y);
    ((uint2*)g_xh)[i] = ph;
    ((uint2*)g_xl)[i] = pl;
    if (blockIdx.x == 0 && threadIdx.x < EE) g_counts[threadIdx.x] = 0;
}

// ---------------- router ----------------
__global__ __launch_bounds__(256) void k_router(const float* __restrict__ x,
                                                const float* __restrict__ gate) {
    __shared__ float Xs[32][33];
    __shared__ float Gs[32][68];
    __shared__ float Ls[32][65];
    __shared__ float sM[32], sInv[32];

    const int t0 = blockIdx.x * 32;
    const int tid = threadIdx.x;
    const int tx = tid & 15, ty = tid >> 4;

    float acc[2][4];
#pragma unroll
    for (int i = 0; i < 2; i++)
#pragma unroll
        for (int j = 0; j < 4; j++) acc[i][j] = 0.f;

    for (int k0 = 0; k0 < HH; k0 += 32) {
        {
            int m = tid >> 3, k4 = (tid & 7) * 4;
            float4 v = *(const float4*)(x + (size_t)(t0 + m) * HH + k0 + k4);
            Xs[m][k4 + 0] = v.x; Xs[m][k4 + 1] = v.y;
            Xs[m][k4 + 2] = v.z; Xs[m][k4 + 3] = v.w;
        }
        {
            int k = tid >> 4, j4 = (tid & 15) * 4;
#pragma unroll
            for (int r = 0; r < 2; r++) {
                float4 v = *(const float4*)(gate + (size_t)(k0 + k + r * 16) * EE + j4);
                *(float4*)&Gs[k + r * 16][j4] = v;
            }
        }
        __syncthreads();
#pragma unroll
        for (int kk = 0; kk < 32; kk++) {
            float a0 = Xs[ty * 2 + 0][kk];
            float a1 = Xs[ty * 2 + 1][kk];
            float4 b = *(float4*)&Gs[kk][tx * 4];
            acc[0][0] += a0 * b.x; acc[0][1] += a0 * b.y; acc[0][2] += a0 * b.z; acc[0][3] += a0 * b.w;
            acc[1][0] += a1 * b.x; acc[1][1] += a1 * b.y; acc[1][2] += a1 * b.z; acc[1][3] += a1 * b.w;
        }
        __syncthreads();
    }
#pragma unroll
    for (int mi = 0; mi < 2; mi++)
#pragma unroll
        for (int ni = 0; ni < 4; ni++)
            Ls[ty * 2 + mi][tx * 4 + ni] = acc[mi][ni];
    __syncthreads();

    if (tid < 32) {
        int t = t0 + tid;
        float m1 = -1e30f, m2 = -1e30f;
        int i1 = -1, i2 = -1;
        for (int e = 0; e < EE; e++) {
            float l = Ls[tid][e];
            if (l > m1) { m2 = m1; i2 = i1; m1 = l; i1 = e; }
            else if (l > m2) { m2 = l; i2 = e; }
        }
        float den = 0.f;
        for (int e = 0; e < EE; e++) den += __expf(Ls[tid][e] - m1);
        sM[tid] = m1; sInv[tid] = 1.f / den;
        float e2 = __expf(m2 - m1);
        float s = 1.f + e2;
        g_topk_i[t * 2 + 0] = i1;
        g_topk_i[t * 2 + 1] = i2;
        g_topk_w[t * 2 + 0] = 1.f / s;
        g_topk_w[t * 2 + 1] = e2 / s;
    }
    __syncthreads();

    if (tid < EE) {
        float s = 0.f;
        for (int r = 0; r < 32; r++)
            s += __expf(Ls[r][tid] - sM[r]) * sInv[r];
        g_usage_partial[blockIdx.x * EE + tid] = s;
    }
}

__global__ void k_build_lists() {
    int t = blockIdx.x * blockDim.x + threadIdx.x;
    if (t < TT) {
#pragma unroll
        for (int k = 0; k < TOPK; k++) {
            int e = g_topk_i[t * 2 + k];
            int pos = atomicAdd(&g_counts[e], 1);
            g_list[e * TT + pos] = t * 2 + k;
        }
    }
}

// tiles + lb loss (both tiny, fused; 64 threads)
__global__ void k_build_tiles(float* __restrict__ out_lb) {
    __shared__ int sNT[EE];
    __shared__ int sBase[EE];
    __shared__ float red[64];
    int e = threadIdx.x;  // 64 threads
    for (int i = e; i < NTILES; i += 64) g_tiles[i] = make_int2(-1, 0);
    int nt = (g_counts[e] + 63) >> 6;
    sNT[e] = nt;
    // lb partial
    float s = 0.f;
    for (int b = 0; b < 64; b++) s += g_usage_partial[b * EE + e];
    float u = s / (float)TT;
    red[e] = u * u;
    __syncthreads();
    if (e == 0) {
        int acc = 0;
        for (int i = 0; i < EE; i++) { sBase[i] = acc; acc += sNT[i]; }
    }
    for (int off = 32; off > 0; off >>= 1) {
        if (e < off) red[e] += red[e + off];
        __syncthreads();
    }
    if (e == 0 && out_lb) *out_lb = (float)EE * red[0];
    int base = sBase[e];
    for (int i = 0; i < nt; i++) g_tiles[base + i] = make_int2(e, i * 64);
}

// ================= GEMM A (mma.sync, pipelined): act = silu(x@w1)*(x@w3) =================
// Block: 64 pairs x 64 d; K-chunk 32; 8 warps 2m x 4n (warp tile 32x16), split-bf16.
__global__ __launch_bounds__(256, 2) void k_gemmA(const float* __restrict__ w1,
                                                  const float* __restrict__ w3) {
    __shared__ uint32_t XSh[64][17], XSl[64][17];
    __shared__ uint32_t W1h[64][17], W1l[64][17], W3h[64][17], W3l[64][17];
    __shared__ int sPair[64];

    int2 tile = g_tiles[blockIdx.x];
    if (tile.x < 0) return;
    const int e = tile.x, t0 = tile.y;
    const int d0 = blockIdx.y * 64;
    const int tid = threadIdx.x;
    const int lane = tid & 31, wid = tid >> 5;
    const int g = lane >> 2, q = lane & 3;
    const int warp_m = wid & 1, warp_n = wid >> 1;
    const int cnt = g_counts[e];

    if (tid < 64) {
        int idx = t0 + tid;
        sPair[tid] = (idx < cnt) ? g_list[e * TT + idx] : -1;
    }
    __syncthreads();

    const float* w1e = w1 + (size_t)e * HH * DD;
    const float* w3e = w3 + (size_t)e * HH * DD;

    const int xrow = tid >> 2, xkp = (tid & 3) * 4;
    const int xp = sPair[xrow];
    const __nv_bfloat16* xsh = (xp >= 0) ? (g_xh + (size_t)(xp >> 1) * HH + xkp * 2) : 0;
    const __nv_bfloat16* xsl = (xp >= 0) ? (g_xl + (size_t)(xp >> 1) * HH + xkp * 2) : 0;
    const int dd = tid & 63, q4 = tid >> 6;
    const float* w1p = w1e + (size_t)(q4 * 8) * DD + d0 + dd;
    const float* w3p = w3e + (size_t)(q4 * 8) * DD + d0 + dd;

    float acc1[2][2][4], acc3[2][2][4];
#pragma unroll
    for (int a = 0; a < 2; a++)
#pragma unroll
        for (int b = 0; b < 2; b++)
#pragma unroll
            for (int c = 0; c < 4; c++) { acc1[a][b][c] = 0.f; acc3[a][b][c] = 0.f; }

    // prefetch registers
    uint4 pvh, pvl;
    float pw1[8], pw3[8];
#define GA_LOAD(K0)                                                        \
    {                                                                      \
        pvh = make_uint4(0, 0, 0, 0); pvl = make_uint4(0, 0, 0, 0);        \
        if (xp >= 0) {                                                     \
            pvh = *(const uint4*)(xsh + (K0));                             \
            pvl = *(const uint4*)(xsl + (K0));                             \
        }                                                                  \
        const float* p1 = w1p + (size_t)(K0) * DD;                         \
        const float* p3 = w3p + (size_t)(K0) * DD;                         \
        _Pragma("unroll")                                                  \
        for (int i = 0; i < 8; i++) {                                      \
            pw1[i] = p1[i * DD];                                           \
            pw3[i] = p3[i * DD];                                           \
        }                                                                  \
    }

    GA_LOAD(0)
    const int NC = HH / 32;
    for (int c = 0; c < NC; c++) {
        // stage from regs
        XSh[xrow][xkp + 0] = pvh.x; XSh[xrow][xkp + 1] = pvh.y;
        XSh[xrow][xkp + 2] = pvh.z; XSh[xrow][xkp + 3] = pvh.w;
        XSl[xrow][xkp + 0] = pvl.x; XSl[xrow][xkp + 1] = pvl.y;
        XSl[xrow][xkp + 2] = pvl.z; XSl[xrow][xkp + 3] = pvl.w;
#pragma unroll
        for (int i = 0; i < 4; i++) {
            uint32_t hi, lo;
            split_pack(pw1[2 * i], pw1[2 * i + 1], hi, lo);
            W1h[dd][q4 * 4 + i] = hi; W1l[dd][q4 * 4 + i] = lo;
            split_pack(pw3[2 * i], pw3[2 * i + 1], hi, lo);
            W3h[dd][q4 * 4 + i] = hi; W3l[dd][q4 * 4 + i] = lo;
        }
        __syncthreads();
        if (c + 1 < NC) GA_LOAD((c + 1) * 32)

#pragma unroll
        for (int s = 0; s < 2; s++) {
            const int s8 = s * 8;
            uint32_t ah[2][4], al[2][4];
#pragma unroll
            for (int mf = 0; mf < 2; mf++) {
                int r0 = warp_m * 32 + mf * 16 + g;
                ah[mf][0] = XSh[r0][s8 + q];     ah[mf][1] = XSh[r0 + 8][s8 + q];
                ah[mf][2] = XSh[r0][s8 + 4 + q]; ah[mf][3] = XSh[r0 + 8][s8 + 4 + q];
                al[mf][0] = XSl[r0][s8 + q];     al[mf][1] = XSl[r0 + 8][s8 + q];
                al[mf][2] = XSl[r0][s8 + 4 + q]; al[mf][3] = XSl[r0 + 8][s8 + 4 + q];
            }
#pragma unroll
            for (int nf = 0; nf < 2; nf++) {
                int n = warp_n * 16 + nf * 8 + g;
                uint32_t b1h[2] = { W1h[n][s8 + q], W1h[n][s8 + 4 + q] };
                uint32_t b1l[2] = { W1l[n][s8 + q], W1l[n][s8 + 4 + q] };
                uint32_t b3h[2] = { W3h[n][s8 + q], W3h[n][s8 + 4 + q] };
                uint32_t b3l[2] = { W3l[n][s8 + q], W3l[n][s8 + 4 + q] };
#pragma unroll
                for (int mf = 0; mf < 2; mf++) {
                    mma16816(acc1[mf][nf], ah[mf], b1h);
                    mma16816(acc1[mf][nf], ah[mf], b1l);
                    mma16816(acc1[mf][nf], al[mf], b1h);
                    mma16816(acc3[mf][nf], ah[mf], b3h);
                    mma16816(acc3[mf][nf], ah[mf], b3l);
                    mma16816(acc3[mf][nf], al[mf], b3h);
                }
            }
        }
        __syncthreads();
    }

    // epilogue: silu(h)*g, split, write act directly from fragments
#pragma unroll
    for (int mf = 0; mf < 2; mf++) {
        int rbase = warp_m * 32 + mf * 16 + g;
#pragma unroll
        for (int half = 0; half < 2; half++) {
            int r = rbase + half * 8;
            int p = sPair[r];
            if (p < 0) continue;
#pragma unroll
            for (int nf = 0; nf < 2; nf++) {
                int dcol = d0 + warp_n * 16 + nf * 8 + q * 2;
                float h0 = acc1[mf][nf][half * 2 + 0], g0 = acc3[mf][nf][half * 2 + 0];
                float h1 = acc1[mf][nf][half * 2 + 1], g1 = acc3[mf][nf][half * 2 + 1];
                float o0 = h0 * g0 / (1.f + __expf(-h0));
                float o1 = h1 * g1 / (1.f + __expf(-h1));
                uint32_t hi, lo;
                split_pack(o0, o1, hi, lo);
                *(uint32_t*)(g_ah + (size_t)p * DD + dcol) = hi;
                *(uint32_t*)(g_al + (size_t)p * DD + dcol) = lo;
            }
        }
    }
}

// ================= GEMM B (mma.sync, pipelined): out += cw * (act @ w2) =================
// Block: 64 pairs x 128 h; K-chunk 32; 8 warps 2m x 4n (warp tile 32x32), split-bf16.
__global__ __launch_bounds__(256, 2) void k_gemmB(const float* __restrict__ w2,
                                                  float* __restrict__ out) {
    __shared__ uint32_t ASh[64][17], ASl[64][17];
    __shared__ uint32_t W2h[128][17], W2l[128][17];
    __shared__ int sPair[64];
    __shared__ float sW[64];

    int2 tile = g_tiles[blockIdx.x];
    if (tile.x < 0) return;
    const int e = tile.x, t0 = tile.y;
    const int h0 = blockIdx.y * 128;
    const int tid = threadIdx.x;
    const int lane = tid & 31, wid = tid >> 5;
    const int g = lane >> 2, q = lane & 3;
    const int warp_m = wid & 1, warp_n = wid >> 1;
    const int cnt = g_counts[e];

    if (tid < 64) {
        int idx = t0 + tid;
        int p = (idx < cnt) ? g_list[e * TT + idx] : -1;
        sPair[tid] = p;
        sW[tid] = (p >= 0) ? g_topk_w[p] : 0.f;
    }
    __syncthreads();

    const float* w2e = w2 + (size_t)e * DD * HH;

    const int xrow = tid >> 2, xkp = (tid & 3) * 4;
    const int xp = sPair[xrow];
    const __nv_bfloat16* ash = (xp >= 0) ? (g_ah + (size_t)xp * DD + xkp * 2) : 0;
    const __nv_bfloat16* asl = (xp >= 0) ? (g_al + (size_t)xp * DD + xkp * 2) : 0;
    const int hh = tid & 127, qh = tid >> 7;
    const float* w2p = w2e + (size_t)(qh * 16) * HH + h0 + hh;

    float acc[2][4][4];
#pragma unroll
    for (int a = 0; a < 2; a++)
#pragma unroll
        for (int b = 0; b < 4; b++)
#pragma unroll
            for (int c = 0; c < 4; c++) acc[a][b][c] = 0.f;

    uint4 pvh, pvl;
    float pw2[16];
#define GB_LOAD(K0)                                                        \
    {                                                                      \
        pvh = make_uint4(0, 0, 0, 0); pvl = make_uint4(0, 0, 0, 0);        \
        if (xp >= 0) {                                                     \
            pvh = *(const uint4*)(ash + (K0));                             \
            pvl = *(const uint4*)(asl + (K0));                             \
        }                                                                  \
        const float* p2 = w2p + (size_t)(K0) * HH;                         \
        _Pragma("unroll")                                                  \
        for (int i = 0; i < 16; i++) pw2[i] = p2[i * HH];                  \
    }

    GB_LOAD(0)
    const int NC = DD / 32;
    for (int c = 0; c < NC; c++) {
        ASh[xrow][xkp + 0] = pvh.x; ASh[xrow][xkp + 1] = pvh.y;
        ASh[xrow][xkp + 2] = pvh.z; ASh[xrow][xkp + 3] = pvh.w;
        ASl[xrow][xkp + 0] = pvl.x; ASl[xrow][xkp + 1] = pvl.y;
        ASl[xrow][xkp + 2] = pvl.z; ASl[xrow][xkp + 3] = pvl.w;
#pragma unroll
        for (int i = 0; i < 8; i++) {
            uint32_t hi, lo;
            split_pack(pw2[2 * i], pw2[2 * i + 1], hi, lo);
            W2h[hh][qh * 8 + i] = hi; W2l[hh][qh * 8 + i] = lo;
        }
        __syncthreads();
        if (c + 1 < NC) GB_LOAD((c + 1) * 32)

#pragma unroll
        for (int s = 0; s < 2; s++) {
            const int s8 = s * 8;
            uint32_t ah[2][4], al[2][4];
#pragma unroll
            for (int mf = 0; mf < 2; mf++) {
                int r0 = warp_m * 32 + mf * 16 + g;
                ah[mf][0] = ASh[r0][s8 + q];     ah[mf][1] = ASh[r0 + 8][s8 + q];
                ah[mf][2] = ASh[r0][s8 + 4 + q]; ah[mf][3] = ASh[r0 + 8][s8 + 4 + q];
                al[mf][0] = ASl[r0][s8 + q];     al[mf][1] = ASl[r0 + 8][s8 + q];
                al[mf][2] = ASl[r0][s8 + 4 + q]; al[mf][3] = ASl[r0 + 8][s8 + 4 + q];
            }
#pragma unroll
            for (int nf = 0; nf < 4; nf++) {
                int n = warp_n * 32 + nf * 8 + g;
                uint32_t bh[2] = { W2h[n][s8 + q], W2h[n][s8 + 4 + q] };
                uint32_t bl[2] = { W2l[n][s8 + q], W2l[n][s8 + 4 + q] };
#pragma unroll
                for (int mf = 0; mf < 2; mf++) {
                    mma16816(acc[mf][nf], ah[mf], bh);
                    mma16816(acc[mf][nf], ah[mf], bl);
                    mma16816(acc[mf][nf], al[mf], bh);
                }
            }
        }
        __syncthreads();
    }

    // epilogue: scale by cw, atomicAdd from fragments
#pragma unroll
    for (int mf = 0; mf < 2; mf++) {
        int rbase = warp_m * 32 + mf * 16 + g;
#pragma unroll
        for (int half = 0; half < 2; half++) {
            int r = rbase + half * 8;
            int p = sPair[r];
            if (p < 0) continue;
            int tok = p >> 1;
            float wgt = sW[r];
            float* orow = out + (size_t)tok * HH;
#pragma unroll
            for (int nf = 0; nf < 4; nf++) {
                int hcol = h0 + warp_n * 32 + nf * 8 + q * 2;
                atomicAdd(orow + hcol + 0, acc[mf][nf][half * 2 + 0] * wgt);
                atomicAdd(orow + hcol + 1, acc[mf][nf][half * 2 + 1] * wgt);
            }
        }
    }
}

// ---------------- launch ----------------
extern "C" void kernel_launch(void* const* d_in, const int* in_sizes, int n_in,
                              void* d_out, int out_size) {
    const float* x    = (const float*)d_in[0];
    const float* w1   = (const float*)d_in[1];
    const float* w3   = (const float*)d_in[2];
    const float* w2   = (const float*)d_in[3];
    const float* gate = (const float*)d_in[4];
    float* out = (float*)d_out;
    float* out_lb = (out_size > TT * HH) ? (out + TT * HH) : nullptr;

    k_prep<<<TT * HH / 4 / 256, 256>>>(x, out);
    k_router<<<64, 256>>>(x, gate);
    k_build_lists<<<8, 256>>>();
    k_build_tiles<<<1, 64>>>(out_lb);
    k_gemmA<<<dim3(NTILES, 8), 256>>>(w1, w3);
    k_gemmB<<<dim3(NTILES, 8), 256>>>(w2, out);
}